// round 2
// baseline (speedup 1.0000x reference)
#include <cuda_runtime.h>

#define UU      64
#define IIN     6
#define TLEN    8192
#define BSZ     256
#define MSZ     16
#define UNFOLDS 6
#define EPSV    1e-8f

// Precomputed parameter tables (filled by prep_kernel each launch; deterministic).
// g_P[i*UU+j] = (A, B, wn, wd):
//   tanh arg  z = fma(v_i, A, B)  with A = 0.5*sigma, B = -0.5*sigma*mu
//   num += wn * tanh(z)  (wn = 0.5*w*erev),  den += wd * tanh(z) (wd = 0.5*w)
__device__ float4 g_P[UU * UU];
// Sensory, same structure but affine-in-x folded through input_w/input_b:
// g_SP[i*UU+j] = (SA, SB, swn, swd), z = fma(x_i, SA, SB)
__device__ float4 g_SP[IIN * UU];
// Per-j folded constants:
//   g_Cn[j] = gleak*vleak + sum_i wn_ij + sum_i swn_ij
//   g_Cd[j] = cm_t + gleak + sum_i wd_ij + sum_i swd_ij + EPS
__device__ float g_Cn[UU];
__device__ float g_Cd[UU];
__device__ float g_cmt[UU];

__global__ void prep_kernel(
    const float* __restrict__ gleak, const float* __restrict__ vleak,
    const float* __restrict__ cm,
    const float* __restrict__ sigma, const float* __restrict__ mu,
    const float* __restrict__ w,     const float* __restrict__ erev,
    const float* __restrict__ ssig,  const float* __restrict__ smu,
    const float* __restrict__ sw,    const float* __restrict__ serev,
    const float* __restrict__ iw,    const float* __restrict__ ib)
{
    int id = blockIdx.x * blockDim.x + threadIdx.x;
    if (id < UU * UU) {
        float s = sigma[id], m = mu[id], ww = w[id], e = erev[id];
        g_P[id] = make_float4(0.5f * s, -0.5f * s * m, 0.5f * ww * e, 0.5f * ww);
    }
    if (id < IIN * UU) {
        int i = id / UU;
        float s = ssig[id], m = smu[id], ww = sw[id], e = serev[id];
        // z = 0.5*ssig*((x*iw + ib) - smu) = x*(0.5*ssig*iw) + 0.5*ssig*(ib - smu)
        g_SP[id] = make_float4(0.5f * s * iw[i], 0.5f * s * (ib[i] - m),
                               0.5f * ww * e, 0.5f * ww);
    }
    if (id < UU) {
        int j = id;
        float sn = 0.f, sd = 0.f;
        for (int i = 0; i < UU; i++) {
            float ww = w[i * UU + j];
            sn += 0.5f * ww * erev[i * UU + j];
            sd += 0.5f * ww;
        }
        for (int i = 0; i < IIN; i++) {
            float ww = sw[i * UU + j];
            sn += 0.5f * ww * serev[i * UU + j];
            sd += 0.5f * ww;
        }
        float cmt = cm[j] * (float)UNFOLDS;  // cm / (ELAPSED/ODE_UNFOLDS), ELAPSED=1
        g_cmt[j] = cmt;
        g_Cn[j]  = gleak[j] * vleak[j] + sn;
        g_Cd[j]  = cmt + gleak[j] + sd + EPSV;
    }
}

__device__ __forceinline__ float tanh_fast(float x) {
    float y;
    asm("tanh.approx.f32 %0, %1;" : "=f"(y) : "f"(x));
    return y;
}

// One CTA per batch element. Thread layout: tid = j*4 + ci.
//   j  = postsynaptic neuron (0..63), ci = i-chunk (0..3, 16 presynaptic each).
// Quad (4 consecutive lanes) reduces the PURE partial sums via bfly shuffles;
// the shared base terms (cm_t*v, leak, sensory) are added ONCE after reduction.
// v[64] double-buffered in smem, 1 barrier per unfold.
__global__ void __launch_bounds__(256, 2) ltc_kernel(
    const float* __restrict__ x,
    const float* __restrict__ ow, const float* __restrict__ ob,
    float* __restrict__ out)
{
    const int b   = blockIdx.x;
    const int tid = threadIdx.x;
    const int j   = tid >> 2;
    const int ci  = tid & 3;

    __shared__ alignas(16) float vbuf[2][UU];

    // Main synapse parameters for this thread's 16 (i, j) pairs -> registers.
    float4 mp[16];
#pragma unroll
    for (int k = 0; k < 16; k++)
        mp[k] = g_P[(ci * 16 + k) * UU + j];

    // Sensory params: ci 0..2 own inputs {2ci, 2ci+1}, ci==3 contributes 0.
    float4 sp0 = make_float4(0.f, 0.f, 0.f, 0.f);
    float4 sp1 = make_float4(0.f, 0.f, 0.f, 0.f);
    if (ci < 3) {
        sp0 = g_SP[(2 * ci)     * UU + j];
        sp1 = g_SP[(2 * ci + 1) * UU + j];
    }
    const float Cn  = g_Cn[j];
    const float Cd  = g_Cd[j];
    const float cmt = g_cmt[j];

    float owj = 0.f, obj = 0.f;
    if (ci == 0 && j < MSZ) { owj = ow[j]; obj = ob[j]; }

    if (tid < UU) vbuf[0][tid] = 0.f;
    __syncthreads();

    const float* xb   = x   + (size_t)b * TLEN * IIN;
    float*       outb = out + (size_t)b * TLEN * MSZ;

    float x0 = 0.f, x1 = 0.f;
    if (ci < 3) { x0 = xb[2 * ci]; x1 = xb[2 * ci + 1]; }

    int cur = 0;
    for (int t = 0; t < TLEN; t++) {
        // ---- sensory sums (constant across the 6 unfolds) ----
        float sn = 0.f, sd = 0.f;
        if (ci < 3) {
            float z0 = fmaf(x0, sp0.x, sp0.y);
            float t0 = tanh_fast(z0);
            sn = sp0.z * t0;
            sd = sp0.w * t0;
            float z1 = fmaf(x1, sp1.x, sp1.y);
            float t1 = tanh_fast(z1);
            sn = fmaf(sp1.z, t1, sn);
            sd = fmaf(sp1.w, t1, sd);
        }
        sn += __shfl_xor_sync(0xffffffffu, sn, 1);
        sn += __shfl_xor_sync(0xffffffffu, sn, 2);
        sd += __shfl_xor_sync(0xffffffffu, sd, 1);
        sd += __shfl_xor_sync(0xffffffffu, sd, 2);
        // base terms: added exactly ONCE (after the quad reduction below)
        const float base_n = Cn + sn;
        const float base_d = Cd + sd;

        // ---- prefetch next timestep's x (hidden under ~3K cycles of unfolds) ----
        float nx0 = x0, nx1 = x1;
        {
            int tn = (t + 1 < TLEN) ? (t + 1) : t;
            if (ci < 3) {
                nx0 = xb[tn * IIN + 2 * ci];
                nx1 = xb[tn * IIN + 2 * ci + 1];
            }
        }

        // ---- 6 fused semi-implicit Euler unfolds ----
        float vnew = 0.f;
#pragma unroll 1
        for (int u = 0; u < UNFOLDS; u++) {
            const float vj = vbuf[cur][j];
            const float4* vb4 = (const float4*)vbuf[cur];
            float4 va = vb4[ci * 4 + 0];
            float4 vB = vb4[ci * 4 + 1];
            float4 vC = vb4[ci * 4 + 2];
            float4 vD = vb4[ci * 4 + 3];
            float vr[16] = { va.x, va.y, va.z, va.w,
                             vB.x, vB.y, vB.z, vB.w,
                             vC.x, vC.y, vC.z, vC.w,
                             vD.x, vD.y, vD.z, vD.w };

            // PURE partial sums over this thread's 16 presynaptic i's
            float n0 = 0.f, d0 = 0.f;
            float n1 = 0.f, d1 = 0.f;
#pragma unroll
            for (int k = 0; k < 16; k++) {
                float z  = fmaf(vr[k], mp[k].x, mp[k].y);
                float tt = tanh_fast(z);
                if (k & 1) {
                    n1 = fmaf(mp[k].z, tt, n1);
                    d1 = fmaf(mp[k].w, tt, d1);
                } else {
                    n0 = fmaf(mp[k].z, tt, n0);
                    d0 = fmaf(mp[k].w, tt, d0);
                }
            }
            float n = n0 + n1;
            float d = d0 + d1;
            n += __shfl_xor_sync(0xffffffffu, n, 1);
            n += __shfl_xor_sync(0xffffffffu, n, 2);
            d += __shfl_xor_sync(0xffffffffu, d, 1);
            d += __shfl_xor_sync(0xffffffffu, d, 2);
            // add shared base terms exactly once (per final value)
            n += fmaf(cmt, vj, base_n);
            d += base_d;
            vnew = __fdividef(n, d);

            if (ci == 0) vbuf[cur ^ 1][j] = vnew;
            __syncthreads();
            cur ^= 1;
        }

        // ---- output: first M motor neurons, affine ----
        if (ci == 0 && j < MSZ)
            outb[t * MSZ + j] = fmaf(vnew, owj, obj);

        x0 = nx0;
        x1 = nx1;
    }
}

extern "C" void kernel_launch(void* const* d_in, const int* in_sizes, int n_in,
                              void* d_out, int out_size)
{
    // metadata order (setup_inputs dict order):
    // 0 x, 1 gleak, 2 vleak, 3 cm, 4 sigma, 5 mu, 6 w, 7 erev,
    // 8 sensory_sigma, 9 sensory_mu, 10 sensory_w, 11 sensory_erev,
    // 12 input_w, 13 input_b, 14 output_w, 15 output_b
    const float* x     = (const float*)d_in[0];
    const float* gleak = (const float*)d_in[1];
    const float* vleak = (const float*)d_in[2];
    const float* cm    = (const float*)d_in[3];
    const float* sigma = (const float*)d_in[4];
    const float* mu    = (const float*)d_in[5];
    const float* w     = (const float*)d_in[6];
    const float* erev  = (const float*)d_in[7];
    const float* ssig  = (const float*)d_in[8];
    const float* smu   = (const float*)d_in[9];
    const float* sw    = (const float*)d_in[10];
    const float* serev = (const float*)d_in[11];
    const float* iw    = (const float*)d_in[12];
    const float* ib    = (const float*)d_in[13];
    const float* ow    = (const float*)d_in[14];
    const float* ob    = (const float*)d_in[15];

    prep_kernel<<<(UU * UU + 255) / 256, 256>>>(
        gleak, vleak, cm, sigma, mu, w, erev,
        ssig, smu, sw, serev, iw, ib);

    ltc_kernel<<<BSZ, 256>>>(x, ow, ob, (float*)d_out);
}